// round 2
// baseline (speedup 1.0000x reference)
#include <cuda_runtime.h>
#include <cuda_fp16.h>
#include <cstdint>

// Problem sizes
#define B_ROWS 8192
#define IN_F   1024
#define OUT_F  1024
#define NBASIS 8
#define KDIM   (IN_F * 9)        // 9216: [silu | 8 basis] interleaved per input feature

// Scratch (device globals — no runtime allocation allowed)
__device__ __half g_A[(size_t)B_ROWS * KDIM];   // 144 MB activations fp16
__device__ __half g_W[(size_t)OUT_F * KDIM];    // 18 MB packed weights fp16

// ---------------------------------------------------------------------------
// Prep kernel 1: A[b, i*9+0] = silu(x),  A[b, i*9+1+k] = basis_k(x)
// ---------------------------------------------------------------------------
__device__ __forceinline__ void bspline8(float v, float* out8) {
    const float G[12] = {-2.2f, -1.8f, -1.4f, -1.0f, -0.6f, -0.2f,
                          0.2f,  0.6f,  1.0f,  1.4f,  1.8f,  2.2f};
    float xc = fminf(fmaxf(v, -1.0f), 1.0f);
    float bs[11];
#pragma unroll
    for (int j = 0; j < 11; j++)
        bs[j] = (xc >= G[j] && xc < G[j + 1]) ? 1.0f : 0.0f;
#pragma unroll
    for (int k = 1; k <= 3; k++) {
        float inv = 1.0f / (0.4f * (float)k);
#pragma unroll
        for (int j = 0; j < 11 - 3; j++) {   // only need j < 11-k; extra iters harmless? no — guard:
            // (loop split below to keep exact bounds)
            (void)j;
            break;
        }
#pragma unroll
        for (int j = 0; j < 10; j++) {
            if (j < 11 - k)
                bs[j] = (xc - G[j]) * inv * bs[j] + (G[j + k + 1] - xc) * inv * bs[j + 1];
        }
    }
#pragma unroll
    for (int k = 0; k < 8; k++) out8[k] = bs[k];
}

__global__ void prep_A_kernel(const float* __restrict__ x) {
    int idx = blockIdx.x * blockDim.x + threadIdx.x;
    if (idx >= B_ROWS * IN_F) return;
    float v = x[idx];
    float s = v / (1.0f + expf(-v));     // SiLU
    float bs[8];
    bspline8(v, bs);
    __half* dst = g_A + (size_t)9 * idx;  // row b = idx>>10, col = (idx&1023)*9
    dst[0] = __float2half(s);
#pragma unroll
    for (int k = 0; k < 8; k++) dst[1 + k] = __float2half(bs[k]);
}

// ---------------------------------------------------------------------------
// Prep kernel 2: W[o, i*9+0] = base_w[o,i],  W[o, i*9+1+k] = spline_w[o,i,k]
// ---------------------------------------------------------------------------
__global__ void prep_W_kernel(const float* __restrict__ base_w,
                              const float* __restrict__ spline_w) {
    int idx = blockIdx.x * blockDim.x + threadIdx.x;
    if (idx >= OUT_F * IN_F) return;
    __half* dst = g_W + (size_t)9 * idx;
    dst[0] = __float2half(base_w[idx]);
    const float* sw = spline_w + (size_t)idx * 8;
#pragma unroll
    for (int k = 0; k < 8; k++) dst[1 + k] = __float2half(sw[k]);
}

// ---------------------------------------------------------------------------
// GEMM: C[8192,1024] = A[8192,9216] * W[1024,9216]^T   (fp16 in, fp32 acc)
// Block tile 128x128x32, 8 warps (4M x 2N), warp tile 32x64, mma m16n8k16.
// Shared rows padded to 40 halves (80B) -> bank-conflict-free fragment loads.
// cp.async 2-stage double buffering.
// ---------------------------------------------------------------------------
#define BM 128
#define BN 128
#define BK 32
#define PADK 40
#define NKT (KDIM / BK)   // 288

__device__ __forceinline__ void mma16816(float* c, const uint32_t* a, const uint32_t* b) {
    asm volatile(
        "mma.sync.aligned.m16n8k16.row.col.f32.f16.f16.f32 "
        "{%0,%1,%2,%3}, {%4,%5,%6,%7}, {%8,%9}, {%0,%1,%2,%3};\n"
        : "+f"(c[0]), "+f"(c[1]), "+f"(c[2]), "+f"(c[3])
        : "r"(a[0]), "r"(a[1]), "r"(a[2]), "r"(a[3]), "r"(b[0]), "r"(b[1]));
}

__global__ void __launch_bounds__(256, 1) gemm_kernel(float* __restrict__ C) {
    __shared__ __half sA[2][BM * PADK];
    __shared__ __half sB[2][BN * PADK];

    const int tid = threadIdx.x;
    const int bm = blockIdx.y;     // 0..63
    const int bn = blockIdx.x;     // 0..7

    const __half* Ag = g_A + (size_t)bm * BM * KDIM;
    const __half* Bg = g_W + (size_t)bn * BN * KDIM;

    const int warp = tid >> 5;
    const int lane = tid & 31;
    const int grp = lane >> 2;     // 0..7
    const int thr = lane & 3;      // 0..3
    const int wm = (warp & 3) * 32;
    const int wn = (warp >> 2) * 64;

    float acc[2][8][4];
#pragma unroll
    for (int im = 0; im < 2; im++)
#pragma unroll
        for (int in = 0; in < 8; in++)
#pragma unroll
            for (int r = 0; r < 4; r++) acc[im][in][r] = 0.0f;

    // --- async tile loader ---
    auto load_tile = [&](int kt, int buf) {
        const int koff = kt * BK;
#pragma unroll
        for (int r = 0; r < 2; r++) {
            int chunk = tid + r * 256;        // 0..511
            int row = chunk >> 2;             // 0..127
            int c16 = chunk & 3;              // 0..3 (16B chunks)
            uint32_t sa = (uint32_t)__cvta_generic_to_shared(
                &sA[buf][row * PADK + c16 * 8]);
            const __half* ga = Ag + (size_t)row * KDIM + koff + c16 * 8;
            asm volatile("cp.async.cg.shared.global [%0], [%1], 16;\n" ::"r"(sa), "l"(ga));
            uint32_t sb = (uint32_t)__cvta_generic_to_shared(
                &sB[buf][row * PADK + c16 * 8]);
            const __half* gb = Bg + (size_t)row * KDIM + koff + c16 * 8;
            asm volatile("cp.async.cg.shared.global [%0], [%1], 16;\n" ::"r"(sb), "l"(gb));
        }
        asm volatile("cp.async.commit_group;\n");
    };

    load_tile(0, 0);

#pragma unroll 1
    for (int kt = 0; kt < NKT; kt++) {
        const int buf = kt & 1;
        asm volatile("cp.async.wait_group 0;\n");
        __syncthreads();
        if (kt + 1 < NKT) load_tile(kt + 1, (kt + 1) & 1);

        // compute on buf
#pragma unroll
        for (int ks = 0; ks < 2; ks++) {
            const int ko = ks * 16;
            uint32_t af[2][4];
#pragma unroll
            for (int im = 0; im < 2; im++) {
                const __half* pa = &sA[buf][(wm + im * 16 + grp) * PADK + ko + thr * 2];
                af[im][0] = *(const uint32_t*)(pa);               // (r,   k0-7)
                af[im][1] = *(const uint32_t*)(pa + 8 * PADK);    // (r+8, k0-7)
                af[im][2] = *(const uint32_t*)(pa + 8);           // (r,   k8-15)
                af[im][3] = *(const uint32_t*)(pa + 8 * PADK + 8);// (r+8, k8-15)
            }
            uint32_t bf[8][2];
#pragma unroll
            for (int in = 0; in < 8; in++) {
                const __half* pb = &sB[buf][(wn + in * 8 + grp) * PADK + ko + thr * 2];
                bf[in][0] = *(const uint32_t*)(pb);
                bf[in][1] = *(const uint32_t*)(pb + 8);
            }
#pragma unroll
            for (int im = 0; im < 2; im++)
#pragma unroll
                for (int in = 0; in < 8; in++)
                    mma16816(acc[im][in], af[im], bf[in]);
        }
        __syncthreads();
    }

    // epilogue
#pragma unroll
    for (int im = 0; im < 2; im++) {
        int row0 = bm * BM + wm + im * 16 + grp;
#pragma unroll
        for (int in = 0; in < 8; in++) {
            int col = bn * BN + wn + in * 8 + thr * 2;
            float2 v0 = make_float2(acc[im][in][0], acc[im][in][1]);
            float2 v1 = make_float2(acc[im][in][2], acc[im][in][3]);
            *(float2*)&C[(size_t)row0 * OUT_F + col] = v0;
            *(float2*)&C[(size_t)(row0 + 8) * OUT_F + col] = v1;
        }
    }
}

// ---------------------------------------------------------------------------
extern "C" void kernel_launch(void* const* d_in, const int* in_sizes, int n_in,
                              void* d_out, int out_size) {
    const float* x        = (const float*)d_in[0];   // (8192, 1024)
    const float* base_w   = (const float*)d_in[1];   // (1024, 1024)
    const float* spline_w = (const float*)d_in[2];   // (1024, 1024, 8)
    float* out            = (float*)d_out;           // (8192, 1024)

    prep_W_kernel<<<(OUT_F * IN_F + 255) / 256, 256>>>(base_w, spline_w);
    prep_A_kernel<<<(B_ROWS * IN_F + 255) / 256, 256>>>(x);

    dim3 grid(OUT_F / BN, B_ROWS / BM);   // (8, 64)
    gemm_kernel<<<grid, 256>>>(out);
}

// round 6
// speedup vs baseline: 1.5034x; 1.5034x over previous
#include <cuda_runtime.h>
#include <cuda_fp16.h>
#include <cstdint>

// ---------------------------------------------------------------------------
// out[8192,1024] = SiLU(x)@Wb^T + einsum('bik,oik->bo', basis(x), Ws)
// Fused as one GEMM: C = A @ W^T, A[8192,9216] fp16, W[1024,9216] fp16.
// K is BASIS-MAJOR: k = j*1024 + i (j=0: silu, j=1..8: basis_{j-1})
// -> fully coalesced prep writes; GEMM invariant to K permutation.
// NOTE: harness ptxas targets plain sm_103 (no tcgen05) -> optimized
// mma.sync HMMA path: 4-stage cp.async, ldmatrix.x4, 2 CTA/SM.
// ---------------------------------------------------------------------------
#define B_ROWS 8192
#define IN_F   1024
#define OUT_F  1024
#define KDIM   9216

__device__ __half g_A[(size_t)B_ROWS * KDIM];   // 144 MB
__device__ __half g_W[(size_t)OUT_F * KDIM];    // 18 MB

// ===========================================================================
// Prep kernels (basis-major K: 9 coalesced half2 streams)
// ===========================================================================
__device__ __forceinline__ void bspline8(float v, float* out8) {
    const float G[12] = {-2.2f, -1.8f, -1.4f, -1.0f, -0.6f, -0.2f,
                          0.2f,  0.6f,  1.0f,  1.4f,  1.8f,  2.2f};
    float xc = fminf(fmaxf(v, -1.0f), 1.0f);
    float bs[11];
#pragma unroll
    for (int j = 0; j < 11; j++)
        bs[j] = (xc >= G[j] && xc < G[j + 1]) ? 1.0f : 0.0f;
#pragma unroll
    for (int k = 1; k <= 3; k++) {
        float inv = 1.0f / (0.4f * (float)k);
#pragma unroll
        for (int j = 0; j < 10; j++) {
            if (j <= 10 - k)
                bs[j] = (xc - G[j]) * inv * bs[j] + (G[j + k + 1] - xc) * inv * bs[j + 1];
        }
    }
#pragma unroll
    for (int k = 0; k < 8; k++) out8[k] = bs[k];
}

__global__ void prep_A_kernel(const float* __restrict__ x) {
    int idx = blockIdx.x * blockDim.x + threadIdx.x;   // 8192*512 half2 slots
    if (idx >= B_ROWS * (IN_F / 2)) return;
    int b = idx >> 9;
    int i2 = idx & 511;
    float2 xv = reinterpret_cast<const float2*>(x)[idx];
    float s0 = xv.x / (1.0f + expf(-xv.x));
    float s1 = xv.y / (1.0f + expf(-xv.y));
    float b0[8], b1[8];
    bspline8(xv.x, b0);
    bspline8(xv.y, b1);
    __half2* row = reinterpret_cast<__half2*>(g_A + (size_t)b * KDIM);
    row[i2] = __floats2half2_rn(s0, s1);
#pragma unroll
    for (int j = 0; j < 8; j++)
        row[(j + 1) * 512 + i2] = __floats2half2_rn(b0[j], b1[j]);
}

__global__ void prep_W_kernel(const float* __restrict__ base_w,
                              const float* __restrict__ spline_w) {
    int idx = blockIdx.x * blockDim.x + threadIdx.x;   // 1024*512 half2 slots
    if (idx >= OUT_F * (IN_F / 2)) return;
    int o = idx >> 9;
    int i2 = idx & 511;
    float2 bw = reinterpret_cast<const float2*>(base_w)[idx];
    const float* sw = spline_w + ((size_t)idx * 2) * 8;   // 16 contiguous floats
    __half2* row = reinterpret_cast<__half2*>(g_W + (size_t)o * KDIM);
    row[i2] = __floats2half2_rn(bw.x, bw.y);
#pragma unroll
    for (int j = 0; j < 8; j++)
        row[(j + 1) * 512 + i2] = __floats2half2_rn(sw[j], sw[8 + j]);
}

// ===========================================================================
// GEMM: C[8192,1024] = A @ W^T.  Block 128x128x32, 8 warps (4M x 2N),
// warp tile 32x64, mma m16n8k16 f32.f16. 4-stage cp.async, ldmatrix.x4.
// PADK=40 halves (80B rows): conflict-free for both LDSM 8-row phases and
// scalar access. 2 CTAs/SM.
// ===========================================================================
#define BM 128
#define BN 128
#define BK 32
#define PADK 40
#define NSTG 4
#define NKT (KDIM / BK)                       // 288
#define STG_HALVES (2 * BM * PADK)            // A+B per stage = 10240 halves
#define SMEM_BYTES (NSTG * STG_HALVES * 2)    // 81920 B

__device__ __forceinline__ void mma16816(float* c, const uint32_t* a, const uint32_t* b) {
    asm volatile(
        "mma.sync.aligned.m16n8k16.row.col.f32.f16.f16.f32 "
        "{%0,%1,%2,%3}, {%4,%5,%6,%7}, {%8,%9}, {%0,%1,%2,%3};\n"
        : "+f"(c[0]), "+f"(c[1]), "+f"(c[2]), "+f"(c[3])
        : "r"(a[0]), "r"(a[1]), "r"(a[2]), "r"(a[3]), "r"(b[0]), "r"(b[1]));
}

__device__ __forceinline__ void ldsm_x4(uint32_t* r, uint32_t addr) {
    asm volatile("ldmatrix.sync.aligned.m8n8.x4.shared.b16 {%0,%1,%2,%3}, [%4];"
        : "=r"(r[0]), "=r"(r[1]), "=r"(r[2]), "=r"(r[3]) : "r"(addr));
}

__global__ void __launch_bounds__(256, 2) gemm_kernel(float* __restrict__ C) {
    extern __shared__ __half smem[];
    const uint32_t smem_b = (uint32_t)__cvta_generic_to_shared(smem);

    const int tid = threadIdx.x;
    const int bm = blockIdx.y;
    const int bn = blockIdx.x;

    const __half* Ag = g_A + (size_t)bm * BM * KDIM;
    const __half* Bg = g_W + (size_t)bn * BN * KDIM;

    const int warp = tid >> 5;
    const int lane = tid & 31;
    const int grp = lane >> 2;     // 0..7
    const int thr = lane & 3;      // 0..3
    const int wm = (warp & 3) * 32;
    const int wn = (warp >> 2) * 64;

    // ldmatrix lane-dependent offsets (in halves, relative to tile base)
    // A x4: m0=(r0-7,k0-7) m1=(r8-15,k0-7) m2=(r0-7,k8-15) m3=(r8-15,k8-15)
    const int a_row = wm + (lane & 15);
    const int a_col = (lane >> 4) * 8;
    // B x4 per pair p: m0=(n0-7,k0-7) m1=(n0-7,k8-15) m2=(n8-15,k0-7) m3=(n8-15,k8-15)
    const int b_row = wn + ((lane >> 4) << 3) + (lane & 7);
    const int b_col = ((lane >> 3) & 1) * 8;

    float acc[2][8][4];
#pragma unroll
    for (int im = 0; im < 2; im++)
#pragma unroll
        for (int in = 0; in < 8; in++)
#pragma unroll
            for (int r = 0; r < 4; r++) acc[im][in][r] = 0.0f;

    // cp.async tile loader: stage st layout = [A: BM*PADK | B: BM*PADK] halves
    const int ld_row = tid >> 1;               // 0..127
    const int ld_c16a = (tid & 1) * 2;         // chunk pairs
    auto load_tile = [&](int kt, int st) {
        const int koff = kt * BK;
        const uint32_t stg = smem_b + st * (STG_HALVES * 2);
#pragma unroll
        for (int c = 0; c < 2; c++) {
            const int c16 = ld_c16a + c;       // 0..3 (16B chunks in 64B row)
            uint32_t sa = stg + (ld_row * PADK + c16 * 8) * 2;
            const __half* ga = Ag + (size_t)ld_row * KDIM + koff + c16 * 8;
            asm volatile("cp.async.cg.shared.global [%0], [%1], 16;\n" ::"r"(sa), "l"(ga));
            uint32_t sb2 = stg + (BM * PADK + ld_row * PADK + c16 * 8) * 2;
            const __half* gb = Bg + (size_t)ld_row * KDIM + koff + c16 * 8;
            asm volatile("cp.async.cg.shared.global [%0], [%1], 16;\n" ::"r"(sb2), "l"(gb));
        }
        asm volatile("cp.async.commit_group;\n");
    };

    // prologue: stages 0..2 in flight
    load_tile(0, 0);
    load_tile(1, 1);
    load_tile(2, 2);

#pragma unroll 1
    for (int kt = 0; kt < NKT; kt++) {
        const int st = kt & 3;
        // stage kt complete when <=2 groups pending (kt+1, kt+2)
        asm volatile("cp.async.wait_group 2;\n");
        __syncthreads();
        if (kt + 3 < NKT) load_tile(kt + 3, (kt + 3) & 3);

        const uint32_t stg = smem_b + st * (STG_HALVES * 2);
#pragma unroll
        for (int ks = 0; ks < 2; ks++) {
            const int ko = ks * 16;
            uint32_t af[2][4];
#pragma unroll
            for (int im = 0; im < 2; im++)
                ldsm_x4(af[im], stg + ((a_row + im * 16) * PADK + a_col + ko) * 2);
            uint32_t bq[4][4];
#pragma unroll
            for (int p = 0; p < 4; p++)
                ldsm_x4(bq[p], stg + (BM * PADK + (b_row + p * 16) * PADK + b_col + ko) * 2);
#pragma unroll
            for (int im = 0; im < 2; im++)
#pragma unroll
                for (int p = 0; p < 4; p++) {
                    uint32_t b0[2] = {bq[p][0], bq[p][1]};
                    uint32_t b1[2] = {bq[p][2], bq[p][3]};
                    mma16816(acc[im][2 * p + 0], af[im], b0);
                    mma16816(acc[im][2 * p + 1], af[im], b1);
                }
        }
    }

    // epilogue
#pragma unroll
    for (int im = 0; im < 2; im++) {
        int row0 = bm * BM + wm + im * 16 + grp;
#pragma unroll
        for (int in = 0; in < 8; in++) {
            int col = bn * BN + wn + in * 8 + thr * 2;
            float2 v0 = make_float2(acc[im][in][0], acc[im][in][1]);
            float2 v1 = make_float2(acc[im][in][2], acc[im][in][3]);
            *(float2*)&C[(size_t)row0 * OUT_F + col] = v0;
            *(float2*)&C[(size_t)(row0 + 8) * OUT_F + col] = v1;
        }
    }
}

// ===========================================================================
extern "C" void kernel_launch(void* const* d_in, const int* in_sizes, int n_in,
                              void* d_out, int out_size) {
    const float* x        = (const float*)d_in[0];   // (8192, 1024)
    const float* base_w   = (const float*)d_in[1];   // (1024, 1024)
    const float* spline_w = (const float*)d_in[2];   // (1024, 1024, 8)
    float* out            = (float*)d_out;           // (8192, 1024)

    cudaFuncSetAttribute(gemm_kernel,
                         cudaFuncAttributeMaxDynamicSharedMemorySize, SMEM_BYTES);

    prep_W_kernel<<<(OUT_F * (IN_F / 2) + 255) / 256, 256>>>(base_w, spline_w);
    prep_A_kernel<<<(B_ROWS * (IN_F / 2) + 255) / 256, 256>>>(x);

    dim3 grid(OUT_F / BN, B_ROWS / BM);   // (8, 64)
    gemm_kernel<<<grid, 256, SMEM_BYTES>>>(out);
}

// round 7
// speedup vs baseline: 2.6525x; 1.7643x over previous
#include <cuda_runtime.h>
#include <cuda_fp16.h>
#include <cuda.h>
#include <cstdint>
#include <dlfcn.h>

// ---------------------------------------------------------------------------
// out[8192,1024] = SiLU(x)@Wb^T + einsum('bik,oik->bo', basis(x), Ws)
// One GEMM: C = A @ W^T, A[8192,9216] fp16, W[1024,9216] fp16 (basis-major K).
// sm_103 (no tcgen05) -> mma.sync HMMA, but TMA + mbarrier pipeline IS legal:
// warp-specialized producer/consumer, 6-stage ring, no per-iter syncthreads.
// ---------------------------------------------------------------------------
#define B_ROWS 8192
#define IN_F   1024
#define OUT_F  1024
#define KDIM   9216

__device__ __align__(1024) __half g_A[(size_t)B_ROWS * KDIM];   // 144 MB
__device__ __align__(1024) __half g_W[(size_t)OUT_F * KDIM];    // 18 MB

// ===========================================================================
// PTX helpers
// ===========================================================================
__device__ __forceinline__ uint32_t smem_u32(const void* p) {
    uint32_t a;
    asm("{ .reg .u64 t; cvta.to.shared.u64 t, %1; cvt.u32.u64 %0, t; }" : "=r"(a) : "l"(p));
    return a;
}
__device__ __forceinline__ uint32_t elect_one() {
    uint32_t pred;
    asm volatile("{\n .reg .pred p;\n elect.sync _|p, 0xFFFFFFFF;\n selp.b32 %0, 1, 0, p;\n}" : "=r"(pred));
    return pred;
}
#define MBAR_INIT(addr, cnt) \
    asm volatile("mbarrier.init.shared.b64 [%0], %1;" :: "r"(addr), "r"((uint32_t)(cnt)) : "memory")
#define MBAR_EXPECT_TX(addr, bytes) \
    asm volatile("mbarrier.arrive.expect_tx.shared.b64 _, [%0], %1;" :: "r"(addr), "r"((uint32_t)(bytes)) : "memory")
#define MBAR_ARRIVE(addr) \
    asm volatile("mbarrier.arrive.shared.b64 _, [%0];" :: "r"(addr) : "memory")
#define MBAR_WAIT(addr, parity) do {                                          \
    uint32_t _m = (addr); uint32_t _p = (parity); uint32_t _d;                \
    asm volatile("{\n .reg .pred p;\n"                                        \
        " mbarrier.try_wait.parity.acquire.cta.shared::cta.b64 p, [%1], %2;\n"\
        " selp.b32 %0, 1, 0, p;\n}" : "=r"(_d) : "r"(_m), "r"(_p) : "memory");\
    if (!_d) {                                                                \
        asm volatile("{\n .reg .pred P1;\n"                                   \
        "WL_%=:\n"                                                            \
        " mbarrier.try_wait.parity.acquire.cta.shared::cta.b64 P1, [%0], %1, 0x989680;\n" \
        " @P1 bra.uni WD_%=;\n bra.uni WL_%=;\nWD_%=:\n}"                     \
        :: "r"(_m), "r"(_p) : "memory");                                      \
    } } while (0)

__device__ __forceinline__ void tma_load_2d(uint32_t dst, const void* map,
                                            int cx, int cy, uint32_t mbar) {
    asm volatile(
        "cp.async.bulk.tensor.2d.shared::cta.global.tile.mbarrier::complete_tx::bytes "
        "[%0], [%1, {%2, %3}], [%4];"
        :: "r"(dst), "l"(map), "r"(cx), "r"(cy), "r"(mbar) : "memory");
}

__device__ __forceinline__ void mma16816(float* c, const uint32_t* a, const uint32_t* b) {
    asm volatile(
        "mma.sync.aligned.m16n8k16.row.col.f32.f16.f16.f32 "
        "{%0,%1,%2,%3}, {%4,%5,%6,%7}, {%8,%9}, {%0,%1,%2,%3};\n"
        : "+f"(c[0]), "+f"(c[1]), "+f"(c[2]), "+f"(c[3])
        : "r"(a[0]), "r"(a[1]), "r"(a[2]), "r"(a[3]), "r"(b[0]), "r"(b[1]));
}
__device__ __forceinline__ void ldsm_x4(uint32_t* r, uint32_t addr) {
    asm volatile("ldmatrix.sync.aligned.m8n8.x4.shared.b16 {%0,%1,%2,%3}, [%4];"
        : "=r"(r[0]), "=r"(r[1]), "=r"(r[2]), "=r"(r[3]) : "r"(addr));
}

// ===========================================================================
// Prep kernels (basis-major K: 9 coalesced half2 streams)
// ===========================================================================
__device__ __forceinline__ void bspline8(float v, float* out8) {
    const float G[12] = {-2.2f, -1.8f, -1.4f, -1.0f, -0.6f, -0.2f,
                          0.2f,  0.6f,  1.0f,  1.4f,  1.8f,  2.2f};
    float xc = fminf(fmaxf(v, -1.0f), 1.0f);
    float bs[11];
#pragma unroll
    for (int j = 0; j < 11; j++)
        bs[j] = (xc >= G[j] && xc < G[j + 1]) ? 1.0f : 0.0f;
#pragma unroll
    for (int k = 1; k <= 3; k++) {
        float inv = 1.0f / (0.4f * (float)k);
#pragma unroll
        for (int j = 0; j < 10; j++) {
            if (j <= 10 - k)
                bs[j] = (xc - G[j]) * inv * bs[j] + (G[j + k + 1] - xc) * inv * bs[j + 1];
        }
    }
#pragma unroll
    for (int k = 0; k < 8; k++) out8[k] = bs[k];
}

__global__ void prep_A_kernel(const float* __restrict__ x) {
    int idx = blockIdx.x * blockDim.x + threadIdx.x;
    if (idx >= B_ROWS * (IN_F / 2)) return;
    int b = idx >> 9;
    int i2 = idx & 511;
    float2 xv = reinterpret_cast<const float2*>(x)[idx];
    float s0 = xv.x / (1.0f + __expf(-xv.x));
    float s1 = xv.y / (1.0f + __expf(-xv.y));
    float b0[8], b1[8];
    bspline8(xv.x, b0);
    bspline8(xv.y, b1);
    __half2* row = reinterpret_cast<__half2*>(g_A + (size_t)b * KDIM);
    row[i2] = __floats2half2_rn(s0, s1);
#pragma unroll
    for (int j = 0; j < 8; j++)
        row[(j + 1) * 512 + i2] = __floats2half2_rn(b0[j], b1[j]);
}

__global__ void prep_W_kernel(const float* __restrict__ base_w,
                              const float* __restrict__ spline_w) {
    int idx = blockIdx.x * blockDim.x + threadIdx.x;
    if (idx >= OUT_F * (IN_F / 2)) return;
    int o = idx >> 9;
    int i2 = idx & 511;
    float2 bw = reinterpret_cast<const float2*>(base_w)[idx];
    const float* sw = spline_w + ((size_t)idx * 2) * 8;
    __half2* row = reinterpret_cast<__half2*>(g_W + (size_t)o * KDIM);
    row[i2] = __floats2half2_rn(bw.x, bw.y);
#pragma unroll
    for (int j = 0; j < 8; j++)
        row[(j + 1) * 512 + i2] = __floats2half2_rn(sw[j], sw[8 + j]);
}

// ===========================================================================
// GEMM: TMA producer warp + 8 mma.sync consumer warps, 6-stage ring.
// Tile: BM=128, BN=128, BK=64 halves (128B rows, SW128).
// Swizzle: byte chunk' (16B units within 128B row) = chunk ^ (row & 7).
// ===========================================================================
#define BM 128
#define BN 128
#define BK 64
#define NSTG 6
#define KTILES (KDIM / BK)                    // 144
#define A_BYTES (BM * BK * 2)                 // 16384
#define B_BYTES (BN * BK * 2)                 // 16384
#define STG_BYTES (A_BYTES + B_BYTES)         // 32768
#define SMEM_BARS 1024
#define SMEM_TOTAL (SMEM_BARS + NSTG * STG_BYTES)   // 197632

__global__ void __launch_bounds__(288, 1) gemm_kernel(
    const __grid_constant__ CUtensorMap tmA,
    const __grid_constant__ CUtensorMap tmB,
    float* __restrict__ C)
{
    extern __shared__ __align__(1024) char smem[];
    const uint32_t sb = smem_u32(smem);
    const uint32_t FULL  = sb;          // 6 x 8B
    const uint32_t EMPTY = sb + 64;     // 6 x 8B
    const uint32_t STG0  = sb + SMEM_BARS;

    const int tid = threadIdx.x;
    const int wid = tid >> 5;
    const int lane = tid & 31;
    const int bm = blockIdx.y;
    const int bn = blockIdx.x;

    if (tid == 0) {
#pragma unroll
        for (int s = 0; s < NSTG; s++) {
            MBAR_INIT(FULL + 8 * s, 1);
            MBAR_INIT(EMPTY + 8 * s, 8);
        }
    }
    __syncthreads();

    if (wid == 8) {
        // ---------------- producer ----------------
        if (elect_one()) {
            int st = 0, ph = 1;                 // phase 1: first empty-wait passes
            for (int s = 0; s < KTILES; s++) {
                MBAR_WAIT(EMPTY + 8 * st, ph);
                const uint32_t buf = STG0 + st * STG_BYTES;
                MBAR_EXPECT_TX(FULL + 8 * st, STG_BYTES);
                tma_load_2d(buf, &tmA, s * BK, bm * BM, FULL + 8 * st);
                tma_load_2d(buf + A_BYTES, &tmB, s * BK, bn * BN, FULL + 8 * st);
                if (++st == NSTG) { st = 0; ph ^= 1; }
            }
        }
        return;
    }

    // ---------------- consumers (warps 0..7) ----------------
    const int grp = lane >> 2;
    const int thr = lane & 3;
    const int wm = (wid & 3) * 32;
    const int wn = (wid >> 2) * 64;

    // ldmatrix per-lane rows (same fragment layout as proven R5 kernel)
    const int hiA = lane >> 4;              // A chunk offset (0/1)
    const int hiB = (lane >> 3) & 1;        // B chunk offset (0/1)
    uint32_t aoff[2]; int ax7[2];
#pragma unroll
    for (int im = 0; im < 2; im++) {
        int r = wm + (lane & 15) + im * 16;
        aoff[im] = (uint32_t)r * 128;
        ax7[im] = r & 7;
    }
    uint32_t boff[4]; int bx7[4];
#pragma unroll
    for (int p = 0; p < 4; p++) {
        int r = wn + p * 16 + ((lane >> 4) << 3) + (lane & 7);
        boff[p] = (uint32_t)r * 128;
        bx7[p] = r & 7;
    }

    float acc[2][8][4];
#pragma unroll
    for (int im = 0; im < 2; im++)
#pragma unroll
        for (int in = 0; in < 8; in++)
#pragma unroll
            for (int r = 0; r < 4; r++) acc[im][in][r] = 0.0f;

    int st = 0, ph = 0;
#pragma unroll 1
    for (int s = 0; s < KTILES; s++) {
        MBAR_WAIT(FULL + 8 * st, ph);
        const uint32_t bufA = STG0 + st * STG_BYTES;
        const uint32_t bufB = bufA + A_BYTES;
#pragma unroll
        for (int ks = 0; ks < 4; ks++) {
            const int cb = 2 * ks;            // base 16B-chunk of this k16 step
            uint32_t af[2][4];
#pragma unroll
            for (int im = 0; im < 2; im++)
                ldsm_x4(af[im], bufA + aoff[im] +
                        (uint32_t)(((cb + hiA) ^ ax7[im]) << 4));
            uint32_t bq[4][4];
#pragma unroll
            for (int p = 0; p < 4; p++)
                ldsm_x4(bq[p], bufB + boff[p] +
                        (uint32_t)(((cb + hiB) ^ bx7[p]) << 4));
#pragma unroll
            for (int im = 0; im < 2; im++)
#pragma unroll
                for (int p = 0; p < 4; p++) {
                    uint32_t b0[2] = {bq[p][0], bq[p][1]};
                    uint32_t b1[2] = {bq[p][2], bq[p][3]};
                    mma16816(acc[im][2 * p + 0], af[im], b0);
                    mma16816(acc[im][2 * p + 1], af[im], b1);
                }
        }
        if (lane == 0) MBAR_ARRIVE(EMPTY + 8 * st);
        if (++st == NSTG) { st = 0; ph ^= 1; }
    }

    // epilogue
#pragma unroll
    for (int im = 0; im < 2; im++) {
        int row0 = bm * BM + wm + im * 16 + grp;
#pragma unroll
        for (int in = 0; in < 8; in++) {
            int col = bn * BN + wn + in * 8 + thr * 2;
            float2 v0 = make_float2(acc[im][in][0], acc[im][in][1]);
            float2 v1 = make_float2(acc[im][in][2], acc[im][in][3]);
            *(float2*)&C[(size_t)row0 * OUT_F + col] = v0;
            *(float2*)&C[(size_t)(row0 + 8) * OUT_F + col] = v1;
        }
    }
}

// ===========================================================================
// Host side
// ===========================================================================
typedef CUresult (*EncodeTiledFn)(
    CUtensorMap*, CUtensorMapDataType, cuuint32_t, void*,
    const cuuint64_t*, const cuuint64_t*, const cuuint32_t*, const cuuint32_t*,
    CUtensorMapInterleave, CUtensorMapSwizzle, CUtensorMapL2promotion,
    CUtensorMapFloatOOBfill);

static EncodeTiledFn get_encode_fn() {
    static EncodeTiledFn fn = nullptr;
    if (!fn) {
        void* h = dlopen("libcuda.so.1", RTLD_NOW | RTLD_GLOBAL);
        if (!h) h = dlopen("libcuda.so", RTLD_NOW | RTLD_GLOBAL);
        if (h) fn = (EncodeTiledFn)dlsym(h, "cuTensorMapEncodeTiled");
    }
    return fn;
}

static void make_map(CUtensorMap* map, void* base, uint64_t rows, uint32_t box_rows) {
    cuuint64_t dims[2]    = {(cuuint64_t)KDIM, (cuuint64_t)rows};
    cuuint64_t strides[1] = {(cuuint64_t)KDIM * sizeof(__half)};
    cuuint32_t box[2]     = {(cuuint32_t)BK, box_rows};
    cuuint32_t estr[2]    = {1, 1};
    get_encode_fn()(map, CU_TENSOR_MAP_DATA_TYPE_FLOAT16, 2, base,
                    dims, strides, box, estr,
                    CU_TENSOR_MAP_INTERLEAVE_NONE, CU_TENSOR_MAP_SWIZZLE_128B,
                    CU_TENSOR_MAP_L2_PROMOTION_L2_128B,
                    CU_TENSOR_MAP_FLOAT_OOB_FILL_NONE);
}

extern "C" void kernel_launch(void* const* d_in, const int* in_sizes, int n_in,
                              void* d_out, int out_size) {
    const float* x        = (const float*)d_in[0];   // (8192, 1024)
    const float* base_w   = (const float*)d_in[1];   // (1024, 1024)
    const float* spline_w = (const float*)d_in[2];   // (1024, 1024, 8)
    float* out            = (float*)d_out;           // (8192, 1024)

    void *pA = nullptr, *pW = nullptr;
    cudaGetSymbolAddress(&pA, g_A);
    cudaGetSymbolAddress(&pW, g_W);

    CUtensorMap tmA, tmB;
    make_map(&tmA, pA, B_ROWS, BM);
    make_map(&tmB, pW, OUT_F, BN);

    cudaFuncSetAttribute(gemm_kernel,
                         cudaFuncAttributeMaxDynamicSharedMemorySize, SMEM_TOTAL);

    prep_W_kernel<<<(OUT_F * (IN_F / 2) + 255) / 256, 256>>>(base_w, spline_w);
    prep_A_kernel<<<(B_ROWS * (IN_F / 2) + 255) / 256, 256>>>(x);

    dim3 grid(OUT_F / BN, B_ROWS / BM);   // (8, 64)
    gemm_kernel<<<grid, 288, SMEM_TOTAL>>>(tmA, tmB, out);
}